// round 2
// baseline (speedup 1.0000x reference)
#include <cuda_runtime.h>
#include <cstdint>

#define BN 8
#define TT 4096
#define CI 1024
#define CO 1024
#define KW 3
#define QP 127.0f

// ---------------- scratch (device globals; no allocation) ----------------
__device__ int8_t g_Xq[(size_t)BN * TT * CI];          // quantized activations [B][T][C]
__device__ int8_t g_Wq[(size_t)KW * CO * CI];          // ternary weights [k][o][i]
__device__ float  g_mu[BN * TT];
__device__ float  g_rstd[BN * TT];
__device__ float  g_absmax[BN * CI];                   // per (b, c) abs-max of x_norm over t
__device__ float  g_wpart[512];
__device__ float  g_beta[1];

// ---------------- helpers ----------------
__device__ __forceinline__ void cp16(void* dst, const void* src, bool pred) {
    unsigned d = (unsigned)__cvta_generic_to_shared(dst);
    int sz = pred ? 16 : 0;
    asm volatile("cp.async.cg.shared.global [%0], [%1], 16, %2;\n"
                 :: "r"(d), "l"(src), "r"(sz));
}

__device__ __forceinline__ void mma_s8(int* c, const unsigned* a, const unsigned* b) {
    asm volatile(
        "mma.sync.aligned.m16n8k32.row.col.s32.s8.s8.s32 "
        "{%0,%1,%2,%3}, {%4,%5,%6,%7}, {%8,%9}, {%0,%1,%2,%3};\n"
        : "+r"(c[0]), "+r"(c[1]), "+r"(c[2]), "+r"(c[3])
        : "r"(a[0]), "r"(a[1]), "r"(a[2]), "r"(a[3]),
          "r"(b[0]), "r"(b[1]));
}

__device__ __forceinline__ int8_t quant8(float xn, float amax) {
    float sc = QP / fmaxf(amax, 1e-5f);
    float q  = rintf(xn * sc);               // round-half-even == jnp.round
    q = fminf(fmaxf(q, -QP), QP);
    return (int8_t)(int)q;
}

// ---------------- kernel 0: zero the atomic-max buffer ----------------
__global__ void k_zero() {
    int i = blockIdx.x * 256 + threadIdx.x;
    if (i < BN * CI) g_absmax[i] = 0.f;
}

// ---------------- kernel 1: LN stats per row + per-(b,c) absmax ----------------
// 256 threads, 32 rows/CTA, each thread owns 4 channels.
__global__ void k_lnstats(const float* __restrict__ x,
                          const float* __restrict__ gam,
                          const float* __restrict__ bet) {
    const int tid = threadIdx.x;
    const int blk = blockIdx.x;                 // 0..1023
    const int b   = blk / (TT / 32);
    const int t0  = (blk % (TT / 32)) * 32;

    float4 g4 = *(const float4*)(gam + tid * 4);
    float4 b4 = *(const float4*)(bet + tid * 4);
    float am0 = 0.f, am1 = 0.f, am2 = 0.f, am3 = 0.f;

    __shared__ float2 wsum[8];

    for (int r = 0; r < 32; ++r) {
        const int row = b * TT + t0 + r;
        float4 v = *(const float4*)(x + (size_t)row * CI + tid * 4);
        float s  = v.x + v.y + v.z + v.w;
        float ss = v.x * v.x + v.y * v.y + v.z * v.z + v.w * v.w;
        #pragma unroll
        for (int o = 16; o; o >>= 1) {
            s  += __shfl_xor_sync(0xffffffffu, s, o);
            ss += __shfl_xor_sync(0xffffffffu, ss, o);
        }
        if ((tid & 31) == 0) wsum[tid >> 5] = make_float2(s, ss);
        __syncthreads();
        if (tid < 32) {
            float2 p = (tid < 8) ? wsum[tid] : make_float2(0.f, 0.f);
            float a = p.x, c = p.y;
            #pragma unroll
            for (int o = 4; o; o >>= 1) {
                a += __shfl_xor_sync(0xffffffffu, a, o);
                c += __shfl_xor_sync(0xffffffffu, c, o);
            }
            if (tid == 0) wsum[0] = make_float2(a, c);
        }
        __syncthreads();
        const float mu  = wsum[0].x * (1.f / CI);
        const float var = wsum[0].y * (1.f / CI) - mu * mu;
        const float rs  = rsqrtf(var + 1e-5f);
        if (tid == 0) { g_mu[row] = mu; g_rstd[row] = rs; }
        __syncthreads();  // protect wsum before next row

        float n;
        n = (v.x - mu) * rs * g4.x + b4.x; am0 = fmaxf(am0, fabsf(n));
        n = (v.y - mu) * rs * g4.y + b4.y; am1 = fmaxf(am1, fabsf(n));
        n = (v.z - mu) * rs * g4.z + b4.z; am2 = fmaxf(am2, fabsf(n));
        n = (v.w - mu) * rs * g4.w + b4.w; am3 = fmaxf(am3, fabsf(n));
    }
    unsigned* gm = (unsigned*)&g_absmax[b * CI + tid * 4];
    atomicMax(gm + 0, __float_as_uint(am0));
    atomicMax(gm + 1, __float_as_uint(am1));
    atomicMax(gm + 2, __float_as_uint(am2));
    atomicMax(gm + 3, __float_as_uint(am3));
}

// ---------------- weight mean(|W|): deterministic two-stage reduce ----------------
__global__ void k_wabs(const float* __restrict__ W) {
    const int tid = threadIdx.x;
    float s = 0.f;
    for (int i = blockIdx.x * 256 + tid; i < CO * CI * KW; i += 512 * 256)
        s += fabsf(W[i]);
    #pragma unroll
    for (int o = 16; o; o >>= 1) s += __shfl_xor_sync(0xffffffffu, s, o);
    __shared__ float ws[8];
    if ((tid & 31) == 0) ws[tid >> 5] = s;
    __syncthreads();
    if (tid == 0) {
        float t = 0.f;
        for (int i = 0; i < 8; ++i) t += ws[i];
        g_wpart[blockIdx.x] = t;
    }
}

__global__ void k_wfinal() {
    const int tid = threadIdx.x;     // 512 threads
    float s = g_wpart[tid];
    #pragma unroll
    for (int o = 16; o; o >>= 1) s += __shfl_xor_sync(0xffffffffu, s, o);
    __shared__ float ws[16];
    if ((tid & 31) == 0) ws[tid >> 5] = s;
    __syncthreads();
    if (tid == 0) {
        float t = 0.f;
        for (int i = 0; i < 16; ++i) t += ws[i];
        g_beta[0] = fmaxf(t / (float)(CO * CI * KW), 1e-5f);
    }
}

// ---------------- weight quant: W[o][i][k] -> g_Wq[k][o][i] ternary ----------------
__global__ void k_wquant(const float* __restrict__ W) {
    const int idx = blockIdx.x * 256 + threadIdx.x;   // o*CI + i, < 1M
    const float beta = g_beta[0];
    #pragma unroll
    for (int k = 0; k < 3; ++k) {
        float ws = W[(size_t)idx * 3 + k] / beta;
        ws = fminf(fmaxf(ws, -1.f), 1.f);
        g_Wq[(size_t)k * (CO * CI) + idx] = (int8_t)(int)rintf(ws);
    }
}

// ---------------- activation quant: recompute LN from cached stats ----------------
__global__ void k_aquant(const float* __restrict__ x,
                         const float* __restrict__ gam,
                         const float* __restrict__ bet) {
    const int row = blockIdx.x;            // b*T + t
    const int b   = row >> 12;             // T = 4096
    const int tid = threadIdx.x;
    const int c   = tid * 4;

    const float mu = __ldg(&g_mu[row]);
    const float rs = __ldg(&g_rstd[row]);
    float4 v  = *(const float4*)(x + (size_t)row * CI + c);
    float4 g4 = *(const float4*)(gam + c);
    float4 b4 = *(const float4*)(bet + c);
    const float* am = &g_absmax[b * CI + c];

    char4 q;
    q.x = quant8((v.x - mu) * rs * g4.x + b4.x, __ldg(am + 0));
    q.y = quant8((v.y - mu) * rs * g4.y + b4.y, __ldg(am + 1));
    q.z = quant8((v.z - mu) * rs * g4.z + b4.z, __ldg(am + 2));
    q.w = quant8((v.w - mu) * rs * g4.w + b4.w, __ldg(am + 3));
    *(char4*)(&g_Xq[(size_t)row * CI + c]) = q;
}

// ---------------- conv as int8 GEMM ----------------
// Y[b][o][t] = sum_{k=0..2} sum_i Wq[k][o][i] * Xq[b][t+k-1][i]
// CTA tile: 128 (o) x 128 (t), BK = 64, K-loop = 3 taps x 16 steps = 48.
// A tile [128][64] row-major (pad to 80B), B tile [128 t][64 i] (pad 80B) —
// both in "row-major over k-dim" form that matches mma .row.col fragments.
__global__ void __launch_bounds__(256)
k_conv(float* __restrict__ out) {
    const int tid = threadIdx.x;
    const int t0  = blockIdx.x * 128;
    const int o0  = blockIdx.y * 128;
    const int b   = blockIdx.z;

    __shared__ union {
        int8_t pipe[4][128 * 80];   // [0],[1]=A stages; [2],[3]=B stages
        float  outb[64 * 132];      // output transpose staging (half tile)
    } sm;
    __shared__ float epi[128];

    if (tid < 128) {
        float gmx = fmaxf(g_absmax[b * CI + o0 + tid], 1e-5f);
        epi[tid] = g_beta[0] * gmx * (1.f / QP);
    }

    const int warp = tid >> 5, lane = tid & 31;
    const int wm = warp & 3, wn = warp >> 2;      // 4x2 warp grid
    const int g  = lane >> 2, tg = lane & 3;

    int acc[2][8][4];
    #pragma unroll
    for (int mi = 0; mi < 2; ++mi)
        #pragma unroll
        for (int ni = 0; ni < 8; ++ni)
            #pragma unroll
            for (int r = 0; r < 4; ++r) acc[mi][ni][r] = 0;

    auto issue = [&](int iter, int stage) {
        const int tap = iter >> 4;
        const int i0  = (iter & 15) << 6;
        const int8_t* Ag = g_Wq + (size_t)tap * (CO * CI) + (size_t)o0 * CI + i0;
        #pragma unroll
        for (int cc = 0; cc < 2; ++cc) {
            const int c   = tid + cc * 256;        // 512 16B chunks per tile
            const int row = c >> 2;
            const int off = (c & 3) * 16;
            cp16(&sm.pipe[stage][row * 80 + off], Ag + (size_t)row * CI + off, true);
            const int tgl = t0 + row + tap - 1;
            const bool p  = (unsigned)tgl < (unsigned)TT;
            const int8_t* Bg = g_Xq + ((size_t)b * TT + (p ? tgl : 0)) * CI + i0 + off;
            cp16(&sm.pipe[2 + stage][row * 80 + off], Bg, p);
        }
    };

    auto compute = [&](int stage) {
        const int8_t* As = sm.pipe[stage];
        const int8_t* Bs = sm.pipe[2 + stage];
        #pragma unroll
        for (int kc = 0; kc < 2; ++kc) {
            unsigned afr[2][4];
            #pragma unroll
            for (int mi = 0; mi < 2; ++mi) {
                const int row = wm * 32 + mi * 16 + g;
                const int8_t* p = As + kc * 32 + 4 * tg;
                afr[mi][0] = *(const unsigned*)(p + row * 80);
                afr[mi][1] = *(const unsigned*)(p + (row + 8) * 80);
                afr[mi][2] = *(const unsigned*)(p + row * 80 + 16);
                afr[mi][3] = *(const unsigned*)(p + (row + 8) * 80 + 16);
            }
            #pragma unroll
            for (int ni = 0; ni < 8; ++ni) {
                const int col = wn * 64 + ni * 8 + g;
                const int8_t* p = Bs + col * 80 + kc * 32 + 4 * tg;
                unsigned bfr[2];
                bfr[0] = *(const unsigned*)(p);
                bfr[1] = *(const unsigned*)(p + 16);
                #pragma unroll
                for (int mi = 0; mi < 2; ++mi) mma_s8(acc[mi][ni], afr[mi], bfr);
            }
        }
    };

    const int NIT = 48;
    issue(0, 0);
    asm volatile("cp.async.commit_group;\n");
    int buf = 0;
    for (int it = 0; it < NIT; ++it) {
        if (it + 1 < NIT) {
            issue(it + 1, buf ^ 1);
            asm volatile("cp.async.commit_group;\n");
            asm volatile("cp.async.wait_group 1;\n");
        } else {
            asm volatile("cp.async.wait_group 0;\n");
        }
        __syncthreads();
        compute(buf);
        __syncthreads();
        buf ^= 1;
    }

    // epilogue: transpose C[o][t] -> out[b][t][o] via SMEM, scale by epi[o]
    #pragma unroll
    for (int h = 0; h < 2; ++h) {
        __syncthreads();
        if (wn == h) {
            #pragma unroll
            for (int mi = 0; mi < 2; ++mi)
                #pragma unroll
                for (int ni = 0; ni < 8; ++ni)
                    #pragma unroll
                    for (int r = 0; r < 4; ++r) {
                        const int ro = wm * 32 + mi * 16 + g + 8 * (r >> 1);
                        const int ct = ni * 8 + 2 * tg + (r & 1);   // 0..63 in half
                        sm.outb[ct * 132 + ro] = (float)acc[mi][ni][r];
                    }
        }
        __syncthreads();
        #pragma unroll
        for (int j = 0; j < 8; ++j) {
            const int f  = tid + j * 256;
            const int tl = f >> 5;
            const int o4 = (f & 31) << 2;
            float4 v = *(float4*)&sm.outb[tl * 132 + o4];
            v.x *= epi[o4 + 0]; v.y *= epi[o4 + 1];
            v.z *= epi[o4 + 2]; v.w *= epi[o4 + 3];
            *(float4*)(out + ((size_t)(b * TT + t0 + h * 64 + tl)) * CO + o0 + o4) = v;
        }
    }
}

// ---------------- launch ----------------
extern "C" void kernel_launch(void* const* d_in, const int* in_sizes, int n_in,
                              void* d_out, int out_size) {
    const float* x   = (const float*)d_in[0];
    const float* gam = (const float*)d_in[1];
    const float* bet = (const float*)d_in[2];
    const float* W   = (const float*)d_in[3];
    float* out = (float*)d_out;

    k_zero<<<32, 256>>>();
    k_lnstats<<<BN * (TT / 32), 256>>>(x, gam, bet);
    k_wabs<<<512, 256>>>(W);
    k_wfinal<<<1, 512>>>();
    k_wquant<<<(CO * CI) / 256, 256>>>(W);
    k_aquant<<<BN * TT, 256>>>(x, gam, bet);
    k_conv<<<dim3(TT / 128, CO / 128, BN), 256>>>(out);
}

// round 4
// speedup vs baseline: 1.0471x; 1.0471x over previous
#include <cuda_runtime.h>
#include <cstdint>

#define BN 8
#define TT 4096
#define CI 1024
#define CO 1024
#define QP 127.0f

// ---------------- scratch (device globals; no allocation) ----------------
__device__ int8_t g_Xq[(size_t)BN * TT * CI];          // quantized activations [B][T][C]
__device__ int8_t g_Wq[(size_t)3 * CO * CI];           // ternary weights [k][o][i]
__device__ float  g_mu[BN * TT];
__device__ float  g_rstd[BN * TT];
__device__ float  g_absmax[BN * CI];
__device__ float  g_wpart[512];
__device__ float  g_beta[1];

// ---------------- helpers ----------------
__device__ __forceinline__ void cp16(void* dst, const void* src, bool pred) {
    unsigned d = (unsigned)__cvta_generic_to_shared(dst);
    int sz = pred ? 16 : 0;
    asm volatile("cp.async.cg.shared.global [%0], [%1], 16, %2;\n"
                 :: "r"(d), "l"(src), "r"(sz));
}

__device__ __forceinline__ void mma_s8(int* c, const unsigned* a, const unsigned* b) {
    asm volatile(
        "mma.sync.aligned.m16n8k32.row.col.s32.s8.s8.s32 "
        "{%0,%1,%2,%3}, {%4,%5,%6,%7}, {%8,%9}, {%0,%1,%2,%3};\n"
        : "+r"(c[0]), "+r"(c[1]), "+r"(c[2]), "+r"(c[3])
        : "r"(a[0]), "r"(a[1]), "r"(a[2]), "r"(a[3]),
          "r"(b[0]), "r"(b[1]));
}

__device__ __forceinline__ void ldsm4(unsigned* r, unsigned saddr) {
    asm volatile("ldmatrix.sync.aligned.m8n8.x4.shared.b16 {%0,%1,%2,%3}, [%4];\n"
                 : "=r"(r[0]), "=r"(r[1]), "=r"(r[2]), "=r"(r[3]) : "r"(saddr));
}

__device__ __forceinline__ int8_t quant8(float xn, float amax) {
    float sc = QP / fmaxf(amax, 1e-5f);
    float q  = rintf(xn * sc);
    q = fminf(fmaxf(q, -QP), QP);
    return (int8_t)(int)q;
}

// ---------------- kernel 0: zero the atomic-max buffer ----------------
__global__ void k_zero() {
    int i = blockIdx.x * 256 + threadIdx.x;
    if (i < BN * CI) g_absmax[i] = 0.f;
}

// ---------------- kernel 1: LN stats per row + per-(b,c) absmax ----------------
__global__ void k_lnstats(const float* __restrict__ x,
                          const float* __restrict__ gam,
                          const float* __restrict__ bet) {
    const int tid = threadIdx.x;
    const int blk = blockIdx.x;
    const int b   = blk / (TT / 32);
    const int t0  = (blk % (TT / 32)) * 32;

    float4 g4 = *(const float4*)(gam + tid * 4);
    float4 b4 = *(const float4*)(bet + tid * 4);
    float am0 = 0.f, am1 = 0.f, am2 = 0.f, am3 = 0.f;

    __shared__ float2 wsum[8];

    for (int r = 0; r < 32; ++r) {
        const int row = b * TT + t0 + r;
        float4 v = *(const float4*)(x + (size_t)row * CI + tid * 4);
        float s  = v.x + v.y + v.z + v.w;
        float ss = v.x * v.x + v.y * v.y + v.z * v.z + v.w * v.w;
        #pragma unroll
        for (int o = 16; o; o >>= 1) {
            s  += __shfl_xor_sync(0xffffffffu, s, o);
            ss += __shfl_xor_sync(0xffffffffu, ss, o);
        }
        if ((tid & 31) == 0) wsum[tid >> 5] = make_float2(s, ss);
        __syncthreads();
        if (tid < 32) {
            float2 p = (tid < 8) ? wsum[tid] : make_float2(0.f, 0.f);
            float a = p.x, c = p.y;
            #pragma unroll
            for (int o = 4; o; o >>= 1) {
                a += __shfl_xor_sync(0xffffffffu, a, o);
                c += __shfl_xor_sync(0xffffffffu, c, o);
            }
            if (tid == 0) wsum[0] = make_float2(a, c);
        }
        __syncthreads();
        const float mu  = wsum[0].x * (1.f / CI);
        const float var = wsum[0].y * (1.f / CI) - mu * mu;
        const float rs  = rsqrtf(var + 1e-5f);
        if (tid == 0) { g_mu[row] = mu; g_rstd[row] = rs; }
        __syncthreads();

        float n;
        n = (v.x - mu) * rs * g4.x + b4.x; am0 = fmaxf(am0, fabsf(n));
        n = (v.y - mu) * rs * g4.y + b4.y; am1 = fmaxf(am1, fabsf(n));
        n = (v.z - mu) * rs * g4.z + b4.z; am2 = fmaxf(am2, fabsf(n));
        n = (v.w - mu) * rs * g4.w + b4.w; am3 = fmaxf(am3, fabsf(n));
    }
    unsigned* gm = (unsigned*)&g_absmax[b * CI + tid * 4];
    atomicMax(gm + 0, __float_as_uint(am0));
    atomicMax(gm + 1, __float_as_uint(am1));
    atomicMax(gm + 2, __float_as_uint(am2));
    atomicMax(gm + 3, __float_as_uint(am3));
}

// ---------------- weight mean(|W|) ----------------
__global__ void k_wabs(const float* __restrict__ W) {
    const int tid = threadIdx.x;
    float s = 0.f;
    for (int i = blockIdx.x * 256 + tid; i < CO * CI * 3; i += 512 * 256)
        s += fabsf(W[i]);
    #pragma unroll
    for (int o = 16; o; o >>= 1) s += __shfl_xor_sync(0xffffffffu, s, o);
    __shared__ float ws[8];
    if ((tid & 31) == 0) ws[tid >> 5] = s;
    __syncthreads();
    if (tid == 0) {
        float t = 0.f;
        for (int i = 0; i < 8; ++i) t += ws[i];
        g_wpart[blockIdx.x] = t;
    }
}

__global__ void k_wfinal() {
    const int tid = threadIdx.x;
    float s = g_wpart[tid];
    #pragma unroll
    for (int o = 16; o; o >>= 1) s += __shfl_xor_sync(0xffffffffu, s, o);
    __shared__ float ws[16];
    if ((tid & 31) == 0) ws[tid >> 5] = s;
    __syncthreads();
    if (tid == 0) {
        float t = 0.f;
        for (int i = 0; i < 16; ++i) t += ws[i];
        g_beta[0] = fmaxf(t / (float)(CO * CI * 3), 1e-5f);
    }
}

// ---------------- weight quant: W[o][i][k] -> g_Wq[k][o][i] ----------------
__global__ void k_wquant(const float* __restrict__ W) {
    const int idx = blockIdx.x * 256 + threadIdx.x;
    const float beta = g_beta[0];
    #pragma unroll
    for (int k = 0; k < 3; ++k) {
        float ws = W[(size_t)idx * 3 + k] / beta;
        ws = fminf(fmaxf(ws, -1.f), 1.f);
        g_Wq[(size_t)k * (CO * CI) + idx] = (int8_t)(int)rintf(ws);
    }
}

// ---------------- activation quant ----------------
__global__ void k_aquant(const float* __restrict__ x,
                         const float* __restrict__ gam,
                         const float* __restrict__ bet) {
    const int row = blockIdx.x;
    const int b   = row >> 12;
    const int tid = threadIdx.x;
    const int c   = tid * 4;

    const float mu = __ldg(&g_mu[row]);
    const float rs = __ldg(&g_rstd[row]);
    float4 v  = *(const float4*)(x + (size_t)row * CI + c);
    float4 g4 = *(const float4*)(gam + c);
    float4 b4 = *(const float4*)(bet + c);
    const float* am = &g_absmax[b * CI + c];

    char4 q;
    q.x = quant8((v.x - mu) * rs * g4.x + b4.x, __ldg(am + 0));
    q.y = quant8((v.y - mu) * rs * g4.y + b4.y, __ldg(am + 1));
    q.z = quant8((v.z - mu) * rs * g4.z + b4.z, __ldg(am + 2));
    q.w = quant8((v.w - mu) * rs * g4.w + b4.w, __ldg(am + 3));
    *(char4*)(&g_Xq[(size_t)row * CI + c]) = q;
}

// ---------------- conv as int8 GEMM (mma.sync + ldmatrix, tap-shared B) -----
// CTA: 128(o) x 128(t). K loop: 16 chunks of 64. Per chunk, one halo B tile
// (130 rows x 64B) serves all 3 taps via shifted base address.
// Stage layout: A3 [tap][128][80] (30720 B) then B [130][80] (10400 B).
#define ASTRIDE 80
#define STAGE_B 41216
#define SMEM_DYN (2 * STAGE_B + 512)

__global__ void __launch_bounds__(256, 2) k_conv(float* __restrict__ out) {
    extern __shared__ char dsm[];
    const unsigned sbase = (unsigned)__cvta_generic_to_shared(dsm);

    const int tid = threadIdx.x;
    const int t0  = blockIdx.x * 128;
    const int o0  = blockIdx.y * 128;
    const int b   = blockIdx.z;

    float* epi = (float*)(dsm + 2 * STAGE_B);
    if (tid < 128)
        epi[tid] = g_beta[0] * fmaxf(g_absmax[b * CI + o0 + tid], 1e-5f) * (1.f / QP);

    const int warp = tid >> 5, lane = tid & 31;
    const int wm = warp & 3, wn = warp >> 2;      // 4x2 warp grid, tile 32(o) x 64(t)
    const int g  = lane >> 2, tg = lane & 3;

    // ldmatrix lane-address bases (bytes within a stage)
    const unsigned aoff = (unsigned)((wm * 32 + (lane & 7) + 8 * ((lane >> 3) & 1)) * ASTRIDE
                                     + ((lane >> 4) << 4));
    const unsigned boff = (unsigned)(30720 + (wn * 64 + (lane & 7) + 8 * (lane >> 4)) * ASTRIDE
                                     + (((lane >> 3) & 1) << 4));

    int acc[2][8][4];
    #pragma unroll
    for (int mi = 0; mi < 2; ++mi)
        #pragma unroll
        for (int ni = 0; ni < 8; ++ni)
            #pragma unroll
            for (int r = 0; r < 4; ++r) acc[mi][ni][r] = 0;

    auto issue = [&](int chunk, int s) {
        char* st = dsm + s * STAGE_B;
        const int i0 = chunk << 6;
        #pragma unroll
        for (int j = 0; j < 9; ++j) {
            const int idx = tid + j * 256;
            if (idx < 1536) {                 // A: 3 taps x 128 rows x 4 chunks
                const int tap = idx >> 9;
                const int rr  = (idx >> 2) & 127;
                const int off = (idx & 3) << 4;
                cp16(st + tap * 10240 + rr * ASTRIDE + off,
                     g_Wq + (size_t)tap * (CO * CI) + (size_t)(o0 + rr) * CI + i0 + off,
                     true);
            } else if (idx < 2056) {          // B: 130 halo rows x 4 chunks
                const int bi = idx - 1536;
                const int rr = bi >> 2;
                const int off = (bi & 3) << 4;
                const int tg2 = t0 - 1 + rr;
                const bool p = (unsigned)tg2 < (unsigned)TT;
                cp16(st + 30720 + rr * ASTRIDE + off,
                     g_Xq + ((size_t)b * TT + (p ? tg2 : 0)) * CI + i0 + off, p);
            }
        }
    };

    auto compute = [&](int s) {
        const unsigned st = sbase + s * STAGE_B;
        #pragma unroll
        for (int tap = 0; tap < 3; ++tap) {
            unsigned afr[2][2][4];    // [mi][kc][4]
            #pragma unroll
            for (int mi = 0; mi < 2; ++mi)
                #pragma unroll
                for (int kc = 0; kc < 2; ++kc)
                    ldsm4(afr[mi][kc],
                          st + tap * 10240 + aoff + mi * (16 * ASTRIDE) + kc * 32);
            #pragma unroll
            for (int p = 0; p < 4; ++p) {
                #pragma unroll
                for (int kc = 0; kc < 2; ++kc) {
                    unsigned bfr[4];
                    ldsm4(bfr, st + boff + (tap + p * 16) * ASTRIDE + kc * 32);
                    #pragma unroll
                    for (int mi = 0; mi < 2; ++mi) {
                        mma_s8(acc[mi][2 * p + 0], afr[mi][kc], bfr + 0);
                        mma_s8(acc[mi][2 * p + 1], afr[mi][kc], bfr + 2);
                    }
                }
            }
        }
    };

    issue(0, 0);
    asm volatile("cp.async.commit_group;\n");
    for (int it = 0; it < 16; ++it) {
        const int s = it & 1;
        if (it + 1 < 16) {
            issue(it + 1, s ^ 1);
            asm volatile("cp.async.commit_group;\n");
            asm volatile("cp.async.wait_group 1;\n");
        } else {
            asm volatile("cp.async.wait_group 0;\n");
        }
        __syncthreads();
        compute(s);
        __syncthreads();
    }

    // ---- epilogue: transpose C[o][t] -> out[b][t][o] via SMEM, scale ----
    float* outb = (float*)dsm;                 // reuse pipe; 64x132 floats
    #pragma unroll
    for (int h = 0; h < 2; ++h) {
        __syncthreads();
        if (wn == h) {
            #pragma unroll
            for (int mi = 0; mi < 2; ++mi)
                #pragma unroll
                for (int ni = 0; ni < 8; ++ni)
                    #pragma unroll
                    for (int r = 0; r < 4; ++r) {
                        const int ro = wm * 32 + mi * 16 + g + 8 * (r >> 1);
                        const int ct = ni * 8 + 2 * tg + (r & 1);
                        outb[ct * 132 + ro] = (float)acc[mi][ni][r];
                    }
        }
        __syncthreads();
        #pragma unroll
        for (int j = 0; j < 8; ++j) {
            const int f  = tid + j * 256;
            const int tl = f >> 5;
            const int o4 = (f & 31) << 2;
            float4 v = *(float4*)&outb[tl * 132 + o4];
            v.x *= epi[o4 + 0]; v.y *= epi[o4 + 1];
            v.z *= epi[o4 + 2]; v.w *= epi[o4 + 3];
            *(float4*)(out + ((size_t)(b * TT + t0 + h * 64 + tl)) * CO + o0 + o4) = v;
        }
    }
}

// ---------------- launch ----------------
extern "C" void kernel_launch(void* const* d_in, const int* in_sizes, int n_in,
                              void* d_out, int out_size) {
    const float* x   = (const float*)d_in[0];
    const float* gam = (const float*)d_in[1];
    const float* bet = (const float*)d_in[2];
    const float* W   = (const float*)d_in[3];
    float* out = (float*)d_out;

    cudaFuncSetAttribute(k_conv, cudaFuncAttributeMaxDynamicSharedMemorySize, SMEM_DYN);

    k_zero<<<32, 256>>>();
    k_lnstats<<<BN * (TT / 32), 256>>>(x, gam, bet);
    k_wabs<<<512, 256>>>(W);
    k_wfinal<<<1, 512>>>();
    k_wquant<<<(CO * CI) / 256, 256>>>(W);
    k_aquant<<<BN * TT, 256>>>(x, gam, bet);
    k_conv<<<dim3(TT / 128, CO / 128, BN), 256, SMEM_DYN>>>(out);
}

// round 5
// speedup vs baseline: 2.3854x; 2.2780x over previous
#include <cuda_runtime.h>
#include <cuda_bf16.h>
#include <cstdint>

#define BN 8
#define TT 4096
#define CI 1024
#define CO 1024
#define QP 127.0f

// ---------------- scratch (device globals; no allocation) ----------------
__device__ __nv_bfloat16 g_Xbf[(size_t)BN * TT * CI];   // quantized activations (bf16 ints)
__device__ __nv_bfloat16 g_Wbf[(size_t)3 * CO * CI];    // ternary weights [k][o][i]
__device__ float  g_mu[BN * TT];
__device__ float  g_rstd[BN * TT];
__device__ float  g_absmax[BN * CI];
__device__ float  g_wpart[512];
__device__ float  g_beta[1];

// ---------------- helpers ----------------
__device__ __forceinline__ void cp16(void* dst, const void* src, bool pred) {
    unsigned d = (unsigned)__cvta_generic_to_shared(dst);
    int sz = pred ? 16 : 0;
    asm volatile("cp.async.cg.shared.global [%0], [%1], 16, %2;\n"
                 :: "r"(d), "l"(src), "r"(sz));
}

__device__ __forceinline__ void mma_bf(float* c, const unsigned* a, const unsigned* b) {
    asm volatile(
        "mma.sync.aligned.m16n8k16.row.col.f32.bf16.bf16.f32 "
        "{%0,%1,%2,%3}, {%4,%5,%6,%7}, {%8,%9}, {%0,%1,%2,%3};\n"
        : "+f"(c[0]), "+f"(c[1]), "+f"(c[2]), "+f"(c[3])
        : "r"(a[0]), "r"(a[1]), "r"(a[2]), "r"(a[3]),
          "r"(b[0]), "r"(b[1]));
}

__device__ __forceinline__ void ldsm4(unsigned* r, unsigned saddr) {
    asm volatile("ldmatrix.sync.aligned.m8n8.x4.shared.b16 {%0,%1,%2,%3}, [%4];\n"
                 : "=r"(r[0]), "=r"(r[1]), "=r"(r[2]), "=r"(r[3]) : "r"(saddr));
}

__device__ __forceinline__ float quantv(float xn, float amax) {
    float sc = QP / fmaxf(amax, 1e-5f);
    float q  = rintf(xn * sc);
    return fminf(fmaxf(q, -QP), QP);
}

// ---------------- launch 0: weight |.| partial sums  (+ zero absmax) -------
__global__ void k_wabs(const float* __restrict__ W) {
    const int tid = threadIdx.x;
    const int z = blockIdx.x * 256 + tid;
    if (z < BN * CI) g_absmax[z] = 0.f;
    float s = 0.f;
    for (int i = blockIdx.x * 256 + tid; i < CO * CI * 3; i += 512 * 256)
        s += fabsf(W[i]);
    #pragma unroll
    for (int o = 16; o; o >>= 1) s += __shfl_xor_sync(0xffffffffu, s, o);
    __shared__ float ws[8];
    if ((tid & 31) == 0) ws[tid >> 5] = s;
    __syncthreads();
    if (tid == 0) {
        float t = 0.f;
        for (int i = 0; i < 8; ++i) t += ws[i];
        g_wpart[blockIdx.x] = t;
    }
}

// ---------------- launch 1: LN stats per row + per-(b,c) absmax -------------
__global__ void k_lnstats(const float* __restrict__ x,
                          const float* __restrict__ gam,
                          const float* __restrict__ bet) {
    const int tid = threadIdx.x;
    const int blk = blockIdx.x;
    const int b   = blk / (TT / 32);
    const int t0  = (blk % (TT / 32)) * 32;

    float4 g4 = *(const float4*)(gam + tid * 4);
    float4 b4 = *(const float4*)(bet + tid * 4);
    float am0 = 0.f, am1 = 0.f, am2 = 0.f, am3 = 0.f;

    __shared__ float2 wsum[8];

    for (int r = 0; r < 32; ++r) {
        const int row = b * TT + t0 + r;
        float4 v = *(const float4*)(x + (size_t)row * CI + tid * 4);
        float s  = v.x + v.y + v.z + v.w;
        float ss = v.x * v.x + v.y * v.y + v.z * v.z + v.w * v.w;
        #pragma unroll
        for (int o = 16; o; o >>= 1) {
            s  += __shfl_xor_sync(0xffffffffu, s, o);
            ss += __shfl_xor_sync(0xffffffffu, ss, o);
        }
        if ((tid & 31) == 0) wsum[tid >> 5] = make_float2(s, ss);
        __syncthreads();
        if (tid < 32) {
            float2 p = (tid < 8) ? wsum[tid] : make_float2(0.f, 0.f);
            float a = p.x, c = p.y;
            #pragma unroll
            for (int o = 4; o; o >>= 1) {
                a += __shfl_xor_sync(0xffffffffu, a, o);
                c += __shfl_xor_sync(0xffffffffu, c, o);
            }
            if (tid == 0) wsum[0] = make_float2(a, c);
        }
        __syncthreads();
        const float mu  = wsum[0].x * (1.f / CI);
        const float var = wsum[0].y * (1.f / CI) - mu * mu;
        const float rs  = rsqrtf(var + 1e-5f);
        if (tid == 0) { g_mu[row] = mu; g_rstd[row] = rs; }
        __syncthreads();

        float n;
        n = (v.x - mu) * rs * g4.x + b4.x; am0 = fmaxf(am0, fabsf(n));
        n = (v.y - mu) * rs * g4.y + b4.y; am1 = fmaxf(am1, fabsf(n));
        n = (v.z - mu) * rs * g4.z + b4.z; am2 = fmaxf(am2, fabsf(n));
        n = (v.w - mu) * rs * g4.w + b4.w; am3 = fmaxf(am3, fabsf(n));
    }
    unsigned* gm = (unsigned*)&g_absmax[b * CI + tid * 4];
    atomicMax(gm + 0, __float_as_uint(am0));
    atomicMax(gm + 1, __float_as_uint(am1));
    atomicMax(gm + 2, __float_as_uint(am2));
    atomicMax(gm + 3, __float_as_uint(am3));
}

// ---------------- launch 2: finalize beta ----------------
__global__ void k_wfinal() {
    const int tid = threadIdx.x;
    float s = g_wpart[tid];
    #pragma unroll
    for (int o = 16; o; o >>= 1) s += __shfl_xor_sync(0xffffffffu, s, o);
    __shared__ float ws[16];
    if ((tid & 31) == 0) ws[tid >> 5] = s;
    __syncthreads();
    if (tid == 0) {
        float t = 0.f;
        for (int i = 0; i < 16; ++i) t += ws[i];
        g_beta[0] = fmaxf(t / (float)(CO * CI * 3), 1e-5f);
    }
}

// ---------------- launch 3: weight quant -> bf16 ternary --------------------
__global__ void k_wquant(const float* __restrict__ W) {
    const int idx = blockIdx.x * 256 + threadIdx.x;
    const float beta = g_beta[0];
    #pragma unroll
    for (int k = 0; k < 3; ++k) {
        float ws = W[(size_t)idx * 3 + k] / beta;
        ws = fminf(fmaxf(ws, -1.f), 1.f);
        g_Wbf[(size_t)k * (CO * CI) + idx] = __float2bfloat16(rintf(ws));
    }
}

// ---------------- launch 4: activation quant -> bf16 ints ------------------
__global__ void k_aquant(const float* __restrict__ x,
                         const float* __restrict__ gam,
                         const float* __restrict__ bet) {
    const int row = blockIdx.x;
    const int b   = row >> 12;
    const int tid = threadIdx.x;
    const int c   = tid * 4;

    const float mu = __ldg(&g_mu[row]);
    const float rs = __ldg(&g_rstd[row]);
    float4 v  = *(const float4*)(x + (size_t)row * CI + c);
    float4 g4 = *(const float4*)(gam + c);
    float4 b4 = *(const float4*)(bet + c);
    const float* am = &g_absmax[b * CI + c];

    __nv_bfloat162 q01, q23;
    q01.x = __float2bfloat16(quantv((v.x - mu) * rs * g4.x + b4.x, __ldg(am + 0)));
    q01.y = __float2bfloat16(quantv((v.y - mu) * rs * g4.y + b4.y, __ldg(am + 1)));
    q23.x = __float2bfloat16(quantv((v.z - mu) * rs * g4.z + b4.z, __ldg(am + 2)));
    q23.y = __float2bfloat16(quantv((v.w - mu) * rs * g4.w + b4.w, __ldg(am + 3)));
    __nv_bfloat162* dst = (__nv_bfloat162*)&g_Xbf[(size_t)row * CI + c];
    dst[0] = q01; dst[1] = q23;
}

// ---------------- launch 5: conv as bf16 GEMM (mma.sync HMMA) --------------
// CTA 128(o) x 128(t). K loop: 32 chunks of 32 elems (64 B/row). Per chunk
// one halo B tile (130 x 64 B) serves all 3 taps via shifted base address.
// Stage: A [tap][128][80B] = 30720 B, B [130][80B] = 10400 B.
#define ASTRIDE 80
#define STAGE_B 41216
#define SMEM_DYN (2 * STAGE_B + 512)

__global__ void __launch_bounds__(256, 2) k_conv(float* __restrict__ out) {
    extern __shared__ char dsm[];
    const unsigned sbase = (unsigned)__cvta_generic_to_shared(dsm);

    const int tid = threadIdx.x;
    const int t0  = blockIdx.x * 128;
    const int o0  = blockIdx.y * 128;
    const int b   = blockIdx.z;

    float* epi = (float*)(dsm + 2 * STAGE_B);
    if (tid < 128)
        epi[tid] = g_beta[0] * fmaxf(g_absmax[b * CI + o0 + tid], 1e-5f) * (1.f / QP);

    const int warp = tid >> 5, lane = tid & 31;
    const int wm = warp & 3, wn = warp >> 2;      // 4x2 warp grid, 32(o) x 64(t)
    const int g  = lane >> 2, tg = lane & 3;

    const unsigned aoff = (unsigned)((wm * 32 + (lane & 7) + 8 * ((lane >> 3) & 1)) * ASTRIDE
                                     + ((lane >> 4) << 4));
    const unsigned boff = (unsigned)(30720 + (wn * 64 + (lane & 7) + 8 * (lane >> 4)) * ASTRIDE
                                     + (((lane >> 3) & 1) << 4));

    float acc[2][8][4];
    #pragma unroll
    for (int mi = 0; mi < 2; ++mi)
        #pragma unroll
        for (int ni = 0; ni < 8; ++ni)
            #pragma unroll
            for (int r = 0; r < 4; ++r) acc[mi][ni][r] = 0.f;

    auto issue = [&](int chunk, int s) {
        char* st = dsm + s * STAGE_B;
        const int i0 = chunk << 5;                  // 32 bf16 elems per chunk
        #pragma unroll
        for (int j = 0; j < 9; ++j) {
            const int idx = tid + j * 256;
            if (idx < 1536) {                 // A: 3 taps x 128 rows x 4 x16B
                const int tap = idx >> 9;
                const int rr  = (idx >> 2) & 127;
                const int off = (idx & 3) << 3;     // elems (8 bf16 = 16 B)
                cp16(st + tap * 10240 + rr * ASTRIDE + (off << 1),
                     g_Wbf + (size_t)tap * (CO * CI) + (size_t)(o0 + rr) * CI + i0 + off,
                     true);
            } else if (idx < 2056) {          // B: 130 halo rows x 4 x16B
                const int bi = idx - 1536;
                const int rr = bi >> 2;
                const int off = (bi & 3) << 3;
                const int tg2 = t0 - 1 + rr;
                const bool p = (unsigned)tg2 < (unsigned)TT;
                cp16(st + 30720 + rr * ASTRIDE + (off << 1),
                     g_Xbf + ((size_t)b * TT + (p ? tg2 : 0)) * CI + i0 + off, p);
            }
        }
    };

    auto compute = [&](int s) {
        const unsigned st = sbase + s * STAGE_B;
        #pragma unroll
        for (int tap = 0; tap < 3; ++tap) {
            unsigned afr[2][2][4];    // [mi][kstep][4]
            #pragma unroll
            for (int mi = 0; mi < 2; ++mi)
                #pragma unroll
                for (int kc = 0; kc < 2; ++kc)
                    ldsm4(afr[mi][kc],
                          st + tap * 10240 + aoff + mi * (16 * ASTRIDE) + kc * 32);
            #pragma unroll
            for (int p = 0; p < 4; ++p) {
                #pragma unroll
                for (int kc = 0; kc < 2; ++kc) {
                    unsigned bfr[4];
                    ldsm4(bfr, st + boff + (tap + p * 16) * ASTRIDE + kc * 32);
                    #pragma unroll
                    for (int mi = 0; mi < 2; ++mi) {
                        mma_bf(acc[mi][2 * p + 0], afr[mi][kc], bfr + 0);
                        mma_bf(acc[mi][2 * p + 1], afr[mi][kc], bfr + 2);
                    }
                }
            }
        }
    };

    issue(0, 0);
    asm volatile("cp.async.commit_group;\n");
    for (int it = 0; it < 32; ++it) {
        const int s = it & 1;
        if (it + 1 < 32) {
            issue(it + 1, s ^ 1);
            asm volatile("cp.async.commit_group;\n");
            asm volatile("cp.async.wait_group 1;\n");
        } else {
            asm volatile("cp.async.wait_group 0;\n");
        }
        __syncthreads();
        compute(s);
        __syncthreads();
    }

    // ---- epilogue: transpose C[o][t] -> out[b][t][o] via SMEM, scale ----
    float* outb = (float*)dsm;
    #pragma unroll
    for (int h = 0; h < 2; ++h) {
        __syncthreads();
        if (wn == h) {
            #pragma unroll
            for (int mi = 0; mi < 2; ++mi)
                #pragma unroll
                for (int ni = 0; ni < 8; ++ni)
                    #pragma unroll
                    for (int r = 0; r < 4; ++r) {
                        const int ro = wm * 32 + mi * 16 + g + 8 * (r >> 1);
                        const int ct = ni * 8 + 2 * tg + (r & 1);
                        outb[ct * 132 + ro] = acc[mi][ni][r];
                    }
        }
        __syncthreads();
        #pragma unroll
        for (int j = 0; j < 8; ++j) {
            const int f  = tid + j * 256;
            const int tl = f >> 5;
            const int o4 = (f & 31) << 2;
            float4 v = *(float4*)&outb[tl * 132 + o4];
            v.x *= epi[o4 + 0]; v.y *= epi[o4 + 1];
            v.z *= epi[o4 + 2]; v.w *= epi[o4 + 3];
            *(float4*)(out + ((size_t)(b * TT + t0 + h * 64 + tl)) * CO + o0 + o4) = v;
        }
    }
}

// ---------------- launch ----------------
extern "C" void kernel_launch(void* const* d_in, const int* in_sizes, int n_in,
                              void* d_out, int out_size) {
    const float* x   = (const float*)d_in[0];
    const float* gam = (const float*)d_in[1];
    const float* bet = (const float*)d_in[2];
    const float* W   = (const float*)d_in[3];
    float* out = (float*)d_out;

    cudaFuncSetAttribute(k_conv, cudaFuncAttributeMaxDynamicSharedMemorySize, SMEM_DYN);

    // launch order chosen so k_conv is launch #5 (ncu -s 5 -c 1 captures it)
    k_wabs<<<512, 256>>>(W);                        // 0 (also zeroes absmax)
    k_lnstats<<<BN * (TT / 32), 256>>>(x, gam, bet);// 1
    k_wfinal<<<1, 512>>>();                         // 2
    k_wquant<<<(CO * CI) / 256, 256>>>(W);          // 3
    k_aquant<<<BN * TT, 256>>>(x, gam, bet);        // 4
    k_conv<<<dim3(TT / 128, CO / 128, BN), 256, SMEM_DYN>>>(out);  // 5
}